// round 12
// baseline (speedup 1.0000x reference)
#include <cuda_runtime.h>
#include <cuda_fp16.h>
#include <math.h>
#include <stdint.h>

#define N_NODES 50000
#define N_EDGES 1600000
#define NT      6250        // edge tiles of 256
#define NNT     391         // node tiles of 128

// ---- pitches
#define PB2  272    // fp16 [.][k=128 pad] (ldmatrix layout / E1 pitch)
#define PBEA 48     // fp16 [.][k=16 pad]

// ---- edge-kernel SMEM offsets (bytes), 256-edge tiles
#define SM_HDN   0           // 256*272 = 69632 (E1 fp16)
#define SM_EA    69632       // 12288
#define SM_W1C   81920       // 6144
#define SM_SIDX  88064       // 1024
#define SM_DIDX  89088       // 1024
#define SM_EIDX  90112       // 1024
#define SMEM_E   91136

// ---- node1 (P/Q) SMEM offsets (dynamic smem of scannode kernel)
#define NSM_X   0
#define NSM_B0  34816
#define NSM_B1  69632
#define NSM_OUT 104448
#define NSM_B1S 139264
#define SMEM_N  139776

// ---- node2 (GEMM2+LN) SMEM offsets
#define N2_W2   0
#define N2_X    34816
#define N2_OUT  69632        // f32 [128][132]
#define N2_B2   137216
#define N2_GAM  137728
#define N2_BET  138240
#define N2_DEG  138752
#define SMEM_N2 139264

// Invariant: g_hsum and g_deg are ZERO at entry of every kernel_launch call
// (zero-initialized at load; node2_kernel re-zeroes its rows at the end).
__device__ float   g_hsum[(size_t)N_NODES * 128];
__device__ __half  g_pq [(size_t)N_NODES * 256];  // [0:128]=P=h@W1a+b1, [128:256]=Q=h@W1b
__device__ int     g_deg [N_NODES];
__device__ int     g_off [N_NODES];
__device__ int     g_eidx[N_EDGES];

// ---------------------------------------------------------------- helpers
__device__ __forceinline__ uint32_t smem_u32(const void* p) {
    uint32_t a;
    asm("{ .reg .u64 t; cvta.to.shared.u64 t, %1; cvt.u32.u64 %0, t; }"
        : "=r"(a) : "l"(p));
    return a;
}
__device__ __forceinline__ void ldsm4(uint32_t* r, uint32_t addr) {
    asm volatile("ldmatrix.sync.aligned.m8n8.x4.shared.b16 {%0,%1,%2,%3}, [%4];"
                 : "=r"(r[0]), "=r"(r[1]), "=r"(r[2]), "=r"(r[3]) : "r"(addr));
}
__device__ __forceinline__ void mma16816(float* c, const uint32_t* a,
                                         const uint32_t* b) {
    asm volatile("mma.sync.aligned.m16n8k16.row.col.f32.f16.f16.f32 "
                 "{%0,%1,%2,%3}, {%4,%5,%6,%7}, {%8,%9}, {%0,%1,%2,%3};"
                 : "+f"(c[0]), "+f"(c[1]), "+f"(c[2]), "+f"(c[3])
                 : "r"(a[0]), "r"(a[1]), "r"(a[2]), "r"(a[3]),
                   "r"(b[0]), "r"(b[1]));
}
__device__ __forceinline__ uint32_t h2bits(float a, float b) {
    __half2 h = __floats2half2_rn(a, b);
    return *reinterpret_cast<uint32_t*>(&h);
}
// exact-GELU via A&S 7.1.26 erf (abs err 1.5e-7)
__device__ __forceinline__ float gelu_fast(float v) {
    const float x = v * 0.70710678118654752440f;
    const float s = fabsf(x);
    float t;
    asm("rcp.approx.f32 %0, %1;" : "=f"(t)
        : "f"(fmaf(0.3275911f, s, 1.0f)));
    const float e = __expf(-s * s);
    float p = fmaf(t, 1.061405429f, -1.453152027f);
    p = fmaf(t, p, 1.421413741f);
    p = fmaf(t, p, -0.284496736f);
    p = fmaf(t, p, 0.254829592f);
    p = p * t;
    const float erfs = fmaf(-p, e, 1.0f);
    return 0.5f * v * (1.0f + copysignf(erfs, x));
}

template <int NCH>
__device__ __forceinline__ void gemm_pass42(float (&c)[2][8][4],
                                            uint32_t abase, uint32_t amstep,
                                            uint32_t bbase, uint32_t bnstep) {
    #pragma unroll
    for (int kc = 0; kc < NCH; ++kc) {
        uint32_t a[2][4], b[4][4];
        ldsm4(a[0], abase);
        ldsm4(a[1], abase + amstep);
        ldsm4(b[0], bbase);
        ldsm4(b[1], bbase + bnstep);
        ldsm4(b[2], bbase + 2 * bnstep);
        ldsm4(b[3], bbase + 3 * bnstep);
        #pragma unroll
        for (int mt = 0; mt < 2; ++mt)
            #pragma unroll
            for (int j = 0; j < 8; ++j)
                mma16816(c[mt][j], a[mt], &b[j >> 1][(j & 1) * 2]);
        abase += 32;
        bbase += 32;
    }
}

// ---------------------------------------------------------------- launch 1: hist
__global__ void hist_kernel(const int* __restrict__ dst) {
    const int base = (blockIdx.x * blockDim.x + threadIdx.x) * 4;
    if (base + 3 < N_EDGES) {
        const int4 d = *reinterpret_cast<const int4*>(dst + base);
        atomicAdd(&g_deg[d.x], 1);
        atomicAdd(&g_deg[d.y], 1);
        atomicAdd(&g_deg[d.z], 1);
        atomicAdd(&g_deg[d.w], 1);
    } else {
        for (int e = base; e < N_EDGES; ++e) atomicAdd(&g_deg[dst[e]], 1);
    }
}

// ---------------------------------------------------------------- launch 2:
// block 0: exclusive scan of g_deg -> g_off;  blocks 1..NNT: node1 (P/Q)
__global__ __launch_bounds__(1024)
void scannode_kernel(const float* __restrict__ h,
                     const float* __restrict__ W1,
                     const float* __restrict__ b1) {
    __shared__ int part[1024];
    extern __shared__ char smbuf[];

    if (blockIdx.x == 0) {
        const int t = threadIdx.x;
        const int start = t * 49;
        const int end   = (start + 49 < N_NODES) ? start + 49 : N_NODES;
        int s = 0;
        for (int i = start; i < end; ++i) s += g_deg[i];
        part[t] = s;
        __syncthreads();
        for (int o = 1; o < 1024; o <<= 1) {
            int v = (t >= o) ? part[t - o] : 0;
            __syncthreads();
            part[t] += v;
            __syncthreads();
        }
        int run = (t == 0) ? 0 : part[t - 1];
        for (int i = start; i < end; ++i) {
            int d = g_deg[i];
            g_off[i] = run;
            run += d;
        }
        return;
    }

    // ---- node1 body (256 threads; rest exit) ----
    if (threadIdx.x >= 256) return;
    const uint32_t sb = smem_u32(smbuf);
    float* b1s = reinterpret_cast<float*>(smbuf + NSM_B1S);

    const int t = threadIdx.x, l = t & 31, warp = t >> 5;
    const int wm = warp & 3, wn = warp >> 2;
    const int grow = t & 127, ghf = t >> 7;

    for (int i = t; i < 128 * 128; i += 256) {
        int k = i >> 7, n = i & 127;
        *reinterpret_cast<__half*>(smbuf + NSM_B0 + n * PB2 + k * 2) =
            __float2half_rn(W1[k * 128 + n]);
        *reinterpret_cast<__half*>(smbuf + NSM_B1 + n * PB2 + k * 2) =
            __float2half_rn(W1[(k + 128) * 128 + n]);
    }
    if (t < 128) b1s[t] = b1[t];

    const uint32_t aoff = ((l & 7) + 8 * ((l >> 3) & 1)) * PB2 + (l >> 4) * 16;
    const uint32_t boff = ((l & 7) + 8 * (l >> 4)) * PB2 + ((l >> 3) & 1) * 16;
    const uint32_t aX  = sb + NSM_X + 32 * wm * PB2 + aoff;
    const uint32_t bB0 = sb + NSM_B0 + 64 * wn * PB2 + boff;
    const uint32_t bB1 = sb + NSM_B1 + 64 * wn * PB2 + boff;
    const int rbase = 32 * wm + (l >> 2);
    const int cbase = 64 * wn + 2 * (l & 3);

    const int node = (blockIdx.x - 1) * 128 + grow;
    const int nc = node < N_NODES ? node : N_NODES - 1;

    {
        const float4* ps = reinterpret_cast<const float4*>(
            h + (size_t)nc * 128 + ghf * 64);
        char* xr = smbuf + NSM_X + grow * PB2 + ghf * 128;
        #pragma unroll
        for (int q = 0; q < 16; ++q) {
            float4 v = ps[q];
            *reinterpret_cast<uint2*>(xr + q * 8) =
                make_uint2(h2bits(v.x, v.y), h2bits(v.z, v.w));
        }
    }
    __syncthreads();

    #pragma unroll
    for (int pass = 0; pass < 2; ++pass) {
        float c[2][8][4];
        #pragma unroll
        for (int mt = 0; mt < 2; ++mt)
            #pragma unroll
            for (int j = 0; j < 8; ++j)
                #pragma unroll
                for (int i = 0; i < 4; ++i) c[mt][j][i] = 0.f;
        gemm_pass42<8>(c, aX, 16 * PB2, pass ? bB1 : bB0, 16 * PB2);
        #pragma unroll
        for (int mt = 0; mt < 2; ++mt)
            #pragma unroll
            for (int j = 0; j < 8; ++j) {
                const int col = cbase + 8 * j;
                const float bb0 = pass ? 0.f : b1s[col];
                const float bb1 = pass ? 0.f : b1s[col + 1];
                #pragma unroll
                for (int rh = 0; rh < 2; ++rh) {
                    const int row = rbase + 16 * mt + 8 * rh;
                    *reinterpret_cast<uint32_t*>(
                        smbuf + NSM_OUT + row * PB2 + col * 2) =
                        h2bits(c[mt][j][2 * rh] + bb0, c[mt][j][2 * rh + 1] + bb1);
                }
            }
        __syncthreads();
        if (node < N_NODES) {
            const uint4* os = reinterpret_cast<const uint4*>(
                smbuf + NSM_OUT + grow * PB2 + ghf * 128);
            uint4* po = reinterpret_cast<uint4*>(
                g_pq + (size_t)node * 256 + pass * 128 + ghf * 64);
            #pragma unroll
            for (int q = 0; q < 8; ++q) po[q] = os[q];
        }
        __syncthreads();
    }
}

// ---------------------------------------------------------------- launch 3: fill
__global__ void fill_kernel(const int* __restrict__ dst) {
    const int base = (blockIdx.x * blockDim.x + threadIdx.x) * 4;
    if (base + 3 < N_EDGES) {
        const int4 d = *reinterpret_cast<const int4*>(dst + base);
        const int p0 = atomicAdd(&g_off[d.x], 1);
        const int p1 = atomicAdd(&g_off[d.y], 1);
        const int p2 = atomicAdd(&g_off[d.z], 1);
        const int p3 = atomicAdd(&g_off[d.w], 1);
        g_eidx[p0] = base;
        g_eidx[p1] = base + 1;
        g_eidx[p2] = base + 2;
        g_eidx[p3] = base + 3;
    } else {
        for (int e = base; e < N_EDGES; ++e) {
            int p = atomicAdd(&g_off[dst[e]], 1);
            g_eidx[p] = e;
        }
    }
}

// ---------------------------------------------------------------- launch 4: edge (PROFILED)
__global__ __launch_bounds__(512, 2)
void edge_mma_kernel(const int*   __restrict__ src,
                     const int*   __restrict__ dst,
                     const float* __restrict__ ea,
                     const float* __restrict__ W1) {
    extern __shared__ char smbuf[];
    const uint32_t sb = smem_u32(smbuf);
    int* sidx  = reinterpret_cast<int*>(smbuf + SM_SIDX);
    int* didx  = reinterpret_cast<int*>(smbuf + SM_DIDX);
    int* eidxs = reinterpret_cast<int*>(smbuf + SM_EIDX);

    const int t = threadIdx.x, l = t & 31, warp = t >> 5;
    const int wm = warp & 3, wn = warp >> 2;       // 4x4 warp grid (E1 MMA)

    // ---- stage W1c^T (fp16) ----
    for (int i = t; i < 16 * 128; i += 512) {
        int k = i >> 7, n = i & 127;
        *reinterpret_cast<__half*>(smbuf + SM_W1C + n * PBEA + k * 2) =
            __float2half_rn(W1[(k + 256) * 128 + n]);
    }

    const uint32_t aoff48 = ((l & 7) + 8 * ((l >> 3) & 1)) * PBEA + (l >> 4) * 16;
    const uint32_t boff48 = ((l & 7) + 8 * (l >> 4)) * PBEA + ((l >> 3) & 1) * 16;
    const uint32_t aEA  = sb + SM_EA  + 64 * wm * PBEA + aoff48;   // 64 rows/warp
    const uint32_t bW1C = sb + SM_W1C + 32 * wn * PBEA + boff48;
    const int rbase = 64 * wm + (l >> 2);
    const int cbase = 32 * wn + 2 * (l & 3);

    // reduction lane map: warp-uniform row, 64 consecutive cols per warp
    const int rg = t >> 6;                          // 0..7 row group
    const int cp = (t & 63) * 2;                    // col pair

    __syncthreads();

    // preload W1c B-fragments (constant over tiles)
    uint32_t bE1[8];
    ldsm4(&bE1[0], bW1C);
    ldsm4(&bE1[4], bW1C + 16 * PBEA);

    for (int tile = blockIdx.x; tile < NT; tile += gridDim.x) {
        const int e0 = tile << 8;                  // 256 edges/tile
        __syncthreads();
        if (t < 256) {
            const int e = g_eidx[e0 + t];
            eidxs[t] = e;
            sidx[t]  = src[e];
            didx[t]  = dst[e];
        }
        __syncthreads();

        // ---- gather EA (2 thr/row) -> SMEM fp16 ----
        {
            const int row = t >> 1, q2 = t & 1;
            const float4* pe = reinterpret_cast<const float4*>(
                ea + (size_t)eidxs[row] * 16 + q2 * 8);
            char* eb = smbuf + SM_EA + row * PBEA + q2 * 16;
            float4 v0 = pe[0], v1 = pe[1];
            *reinterpret_cast<uint4*>(eb) =
                make_uint4(h2bits(v0.x, v0.y), h2bits(v0.z, v0.w),
                           h2bits(v1.x, v1.y), h2bits(v1.z, v1.w));
        }
        __syncthreads();

        // ---- E1 = ea @ W1c^T (K=16), fp16 -> SM_HDN ----
        #pragma unroll
        for (int mt = 0; mt < 4; ++mt) {
            uint32_t a[4];
            ldsm4(a, aEA + mt * 16 * PBEA);
            float c[4][4];
            #pragma unroll
            for (int j = 0; j < 4; ++j)
                #pragma unroll
                for (int i = 0; i < 4; ++i) c[j][i] = 0.f;
            #pragma unroll
            for (int j = 0; j < 4; ++j)
                mma16816(c[j], a, &bE1[(j >> 1) * 4 + (j & 1) * 2]);
            #pragma unroll
            for (int j = 0; j < 4; ++j) {
                const int col = cbase + 8 * j;
                #pragma unroll
                for (int rh = 0; rh < 2; ++rh) {
                    const int row = rbase + 16 * mt + 8 * rh;
                    *reinterpret_cast<uint32_t*>(
                        smbuf + SM_HDN + row * PB2 + col * 2) =
                        h2bits(c[j][2 * rh], c[j][2 * rh + 1]);
                }
            }
        }
        __syncthreads();

        // ---- fused: gelu(P[src]+Q[dst]+E1) + segmented reduction -> g_hsum ----
        {
            const char* pqb = reinterpret_cast<const char*>(g_pq);
            float ax = 0.f, ay = 0.f;
            #pragma unroll 4
            for (int r = 0; r < 32; ++r) {
                const int row = rg * 32 + r;
                const int sN = sidx[row], dN = didx[row];
                const uint32_t e1 = *reinterpret_cast<const uint32_t*>(
                    smbuf + SM_HDN + row * PB2 + cp * 2);
                const uint32_t pv = *reinterpret_cast<const uint32_t*>(
                    pqb + (size_t)sN * 512 + cp * 2);
                const uint32_t qv = *reinterpret_cast<const uint32_t*>(
                    pqb + (size_t)dN * 512 + 256 + cp * 2);
                const __half2 sh = __hadd2(
                    __hadd2(*reinterpret_cast<const __half2*>(&pv),
                            *reinterpret_cast<const __half2*>(&qv)),
                    *reinterpret_cast<const __half2*>(&e1));
                const float2 sf = __half22float2(sh);
                ax += gelu_fast(sf.x);
                ay += gelu_fast(sf.y);
                const bool flush = (r == 31) || (dN != didx[row + 1]);
                if (flush) {
                    asm volatile("red.global.add.v2.f32 [%0], {%1,%2};"
                                 :: "l"(g_hsum + (size_t)dN * 128 + cp),
                                    "f"(ax), "f"(ay) : "memory");
                    ax = 0.f; ay = 0.f;
                }
            }
        }
    }
}

// ---------------------------------------------------------------- launch 5: node2 (+cleanup)
// out = LayerNorm(h + hsum @ W2 + deg*b2); then re-zero own rows of hsum/deg
__global__ __launch_bounds__(256, 1)
void node2_kernel(const float* __restrict__ h,
                  const float* __restrict__ W2,
                  const float* __restrict__ b2,
                  const float* __restrict__ gamma,
                  const float* __restrict__ beta,
                  float* __restrict__ out) {
    extern __shared__ char smbuf[];
    const uint32_t sb = smem_u32(smbuf);
    float* b2s = reinterpret_cast<float*>(smbuf + N2_B2);
    float* gms = reinterpret_cast<float*>(smbuf + N2_GAM);
    float* bts = reinterpret_cast<float*>(smbuf + N2_BET);
    int*   dgs = reinterpret_cast<int*>(smbuf + N2_DEG);
    float* outs = reinterpret_cast<float*>(smbuf + N2_OUT);

    const int t = threadIdx.x, l = t & 31, warp = t >> 5;
    const int wm = warp & 3, wn = warp >> 2;
    const int grow = t & 127, ghf = t >> 7;

    for (int i = t; i < 128 * 128; i += 256) {
        int k = i >> 7, n = i & 127;
        *reinterpret_cast<__half*>(smbuf + N2_W2 + n * PB2 + k * 2) =
            __float2half_rn(W2[i]);
    }
    if (t < 128) { b2s[t] = b2[t]; gms[t] = gamma[t]; bts[t] = beta[t]; }

    const int node = blockIdx.x * 128 + grow;
    const int nc = node < N_NODES ? node : N_NODES - 1;
    if (t >= 128 && t < 256) {
        int nn = blockIdx.x * 128 + (t - 128);
        dgs[t - 128] = (nn < N_NODES) ? g_deg[nn] : 0;
    }

    {
        const float4* ps = reinterpret_cast<const float4*>(
            g_hsum + (size_t)nc * 128 + ghf * 64);
        char* xr = smbuf + N2_X + grow * PB2 + ghf * 128;
        #pragma unroll
        for (int q = 0; q < 16; ++q) {
            float4 v = ps[q];
            *reinterpret_cast<uint2*>(xr + q * 8) =
                make_uint2(h2bits(v.x, v.y), h2bits(v.z, v.w));
        }
    }
    __syncthreads();

    const uint32_t aoff = ((l & 7) + 8 * ((l >> 3) & 1)) * PB2 + (l >> 4) * 16;
    const uint32_t boff = ((l & 7) + 8 * (l >> 4)) * PB2 + ((l >> 3) & 1) * 16;
    const uint32_t aX = sb + N2_X + 32 * wm * PB2 + aoff;
    const uint32_t bW = sb + N2_W2 + 64 * wn * PB2 + boff;
    const int rbase = 32 * wm + (l >> 2);
    const int cbase = 64 * wn + 2 * (l & 3);

    float c[2][8][4];
    #pragma unroll
    for (int mt = 0; mt < 2; ++mt)
        #pragma unroll
        for (int j = 0; j < 8; ++j)
            #pragma unroll
            for (int i = 0; i < 4; ++i) c[mt][j][i] = 0.f;
    gemm_pass42<8>(c, aX, 16 * PB2, bW, 16 * PB2);

    #pragma unroll
    for (int mt = 0; mt < 2; ++mt)
        #pragma unroll
        for (int j = 0; j < 8; ++j) {
            const int col = cbase + 8 * j;
            const float bb0 = b2s[col], bb1 = b2s[col + 1];
            #pragma unroll
            for (int rh = 0; rh < 2; ++rh) {
                const int row = rbase + 16 * mt + 8 * rh;
                const float dg = (float)dgs[row];
                outs[row * 132 + col]     = c[mt][j][2 * rh] + dg * bb0;
                outs[row * 132 + col + 1] = c[mt][j][2 * rh + 1] + dg * bb1;
            }
        }
    __syncthreads();

    for (int r = 0; r < 16; ++r) {
        const int row = warp * 16 + r;
        const int nn = blockIdx.x * 128 + row;
        if (nn >= N_NODES) break;
        const float4 hv = reinterpret_cast<const float4*>(h)[(size_t)nn * 32 + l];
        const float4 av = *reinterpret_cast<const float4*>(outs + row * 132 + l * 4);
        float4 x;
        x.x = hv.x + av.x; x.y = hv.y + av.y;
        x.z = hv.z + av.z; x.w = hv.w + av.w;
        float s = x.x + x.y + x.z + x.w;
        #pragma unroll
        for (int o = 16; o > 0; o >>= 1) s += __shfl_xor_sync(0xffffffffu, s, o);
        const float mu = s * (1.0f / 128.0f);
        const float dx = x.x - mu, dy = x.y - mu, dz = x.z - mu, dw = x.w - mu;
        float q = dx * dx + dy * dy + dz * dz + dw * dw;
        #pragma unroll
        for (int o = 16; o > 0; o >>= 1) q += __shfl_xor_sync(0xffffffffu, q, o);
        const float inv = rsqrtf(q * (1.0f / 128.0f) + 1e-5f);
        float4 o4;
        o4.x = dx * inv * gms[l * 4 + 0] + bts[l * 4 + 0];
        o4.y = dy * inv * gms[l * 4 + 1] + bts[l * 4 + 1];
        o4.z = dz * inv * gms[l * 4 + 2] + bts[l * 4 + 2];
        o4.w = dw * inv * gms[l * 4 + 3] + bts[l * 4 + 3];
        reinterpret_cast<float4*>(out)[(size_t)nn * 32 + l] = o4;
    }

    // ---- cleanup: restore zero-state of this block's hsum rows + deg ----
    {
        const int row0 = blockIdx.x * 128;
        float4* hz = reinterpret_cast<float4*>(g_hsum + (size_t)row0 * 128);
        for (int i = t; i < 128 * 32; i += 256) {
            const int rr = row0 + (i >> 5);
            if (rr < N_NODES) hz[i] = make_float4(0.f, 0.f, 0.f, 0.f);
        }
        if (t < 128) {
            const int nn = row0 + t;
            if (nn < N_NODES) g_deg[nn] = 0;
        }
    }
}

// ----------------------------------------------------------------
extern "C" void kernel_launch(void* const* d_in, const int* in_sizes, int n_in,
                              void* d_out, int out_size) {
    const float* h     = (const float*)d_in[0];
    const int*   src   = (const int*)  d_in[1];
    const int*   dst   = (const int*)  d_in[2];
    const float* ea    = (const float*)d_in[3];
    const float* W1    = (const float*)d_in[4];
    const float* b1    = (const float*)d_in[5];
    const float* W2    = (const float*)d_in[6];
    const float* b2    = (const float*)d_in[7];
    const float* gamma = (const float*)d_in[8];
    const float* beta  = (const float*)d_in[9];
    float*       out   = (float*)d_out;

    static int sm_count = []() {
        int dev = 0, c = 148;
        cudaGetDevice(&dev);
        cudaDeviceGetAttribute(&c, cudaDevAttrMultiProcessorCount, dev);
        return c;
    }();
    static bool attr_ok = []() {
        cudaFuncSetAttribute(edge_mma_kernel,
                             cudaFuncAttributeMaxDynamicSharedMemorySize, SMEM_E);
        cudaFuncSetAttribute(scannode_kernel,
                             cudaFuncAttributeMaxDynamicSharedMemorySize, SMEM_N);
        cudaFuncSetAttribute(node2_kernel,
                             cudaFuncAttributeMaxDynamicSharedMemorySize, SMEM_N2);
        return true;
    }();
    (void)attr_ok;

    hist_kernel<<<(N_EDGES / 4 + 255) / 256, 256>>>(dst);              // 1
    scannode_kernel<<<1 + NNT, 1024, SMEM_N>>>(h, W1, b1);             // 2
    fill_kernel<<<(N_EDGES / 4 + 255) / 256, 256>>>(dst);              // 3
    edge_mma_kernel<<<2 * sm_count, 512, SMEM_E>>>(src, dst, ea, W1);  // 4 <- profiled
    node2_kernel<<<NNT, 256, SMEM_N2>>>(h, W2, b2, gamma, beta, out);  // 5
}

// round 13
// speedup vs baseline: 1.4051x; 1.4051x over previous
#include <cuda_runtime.h>
#include <cuda_fp16.h>
#include <math.h>
#include <stdint.h>

#define N_NODES 50000
#define N_EDGES 1600000
#define NT      6250        // edge tiles of 256
#define NNT     391         // node tiles of 128

// ---- pitches
#define PB2  272    // fp16 [.][k=128 pad] (ldmatrix layout / E1 pitch)
#define PBEA 48     // fp16 [.][k=16 pad]

// ---- edge-kernel SMEM offsets (bytes), 256-edge tiles
#define SM_HDN   0           // 256*272 = 69632 (E1 fp16)
#define SM_EA    69632       // 12288
#define SM_W1C   81920       // 6144
#define SM_SIDX  88064       // 1024
#define SM_DIDX  89088       // 1024
#define SM_EIDX  90112       // 1024
#define SMEM_E   91136

// ---- node1 (P/Q) SMEM offsets (dynamic smem of scannode kernel)
#define NSM_X   0
#define NSM_B0  34816
#define NSM_B1  69632
#define NSM_OUT 104448
#define NSM_B1S 139264
#define SMEM_N  139776

// ---- node2 (GEMM2+LN) SMEM offsets
#define N2_W2   0
#define N2_X    34816
#define N2_OUT  69632        // f32 [128][132]
#define N2_B2   137216
#define N2_GAM  137728
#define N2_BET  138240
#define N2_DEG  138752
#define SMEM_N2 139264

// Invariant: g_hsum and g_deg are ZERO at entry of every kernel_launch call
// (zero-initialized at load; node2_kernel re-zeroes its rows at the end).
__device__ float   g_hsum[(size_t)N_NODES * 128];
__device__ __half  g_pq [(size_t)N_NODES * 256];  // [0:128]=P=h@W1a+b1, [128:256]=Q=h@W1b
__device__ int     g_deg [N_NODES];
__device__ int     g_off [N_NODES];
__device__ int     g_eidx[N_EDGES];

// ---------------------------------------------------------------- helpers
__device__ __forceinline__ uint32_t smem_u32(const void* p) {
    uint32_t a;
    asm("{ .reg .u64 t; cvta.to.shared.u64 t, %1; cvt.u32.u64 %0, t; }"
        : "=r"(a) : "l"(p));
    return a;
}
__device__ __forceinline__ void ldsm4(uint32_t* r, uint32_t addr) {
    asm volatile("ldmatrix.sync.aligned.m8n8.x4.shared.b16 {%0,%1,%2,%3}, [%4];"
                 : "=r"(r[0]), "=r"(r[1]), "=r"(r[2]), "=r"(r[3]) : "r"(addr));
}
__device__ __forceinline__ void mma16816(float* c, const uint32_t* a,
                                         const uint32_t* b) {
    asm volatile("mma.sync.aligned.m16n8k16.row.col.f32.f16.f16.f32 "
                 "{%0,%1,%2,%3}, {%4,%5,%6,%7}, {%8,%9}, {%0,%1,%2,%3};"
                 : "+f"(c[0]), "+f"(c[1]), "+f"(c[2]), "+f"(c[3])
                 : "r"(a[0]), "r"(a[1]), "r"(a[2]), "r"(a[3]),
                   "r"(b[0]), "r"(b[1]));
}
__device__ __forceinline__ uint32_t h2bits(float a, float b) {
    __half2 h = __floats2half2_rn(a, b);
    return *reinterpret_cast<uint32_t*>(&h);
}
// exact-GELU via A&S 7.1.26 erf (abs err 1.5e-7)
__device__ __forceinline__ float gelu_fast(float v) {
    const float x = v * 0.70710678118654752440f;
    const float s = fabsf(x);
    float t;
    asm("rcp.approx.f32 %0, %1;" : "=f"(t)
        : "f"(fmaf(0.3275911f, s, 1.0f)));
    const float e = __expf(-s * s);
    float p = fmaf(t, 1.061405429f, -1.453152027f);
    p = fmaf(t, p, 1.421413741f);
    p = fmaf(t, p, -0.284496736f);
    p = fmaf(t, p, 0.254829592f);
    p = p * t;
    const float erfs = fmaf(-p, e, 1.0f);
    return 0.5f * v * (1.0f + copysignf(erfs, x));
}

template <int NCH>
__device__ __forceinline__ void gemm_pass42(float (&c)[2][8][4],
                                            uint32_t abase, uint32_t amstep,
                                            uint32_t bbase, uint32_t bnstep) {
    #pragma unroll
    for (int kc = 0; kc < NCH; ++kc) {
        uint32_t a[2][4], b[4][4];
        ldsm4(a[0], abase);
        ldsm4(a[1], abase + amstep);
        ldsm4(b[0], bbase);
        ldsm4(b[1], bbase + bnstep);
        ldsm4(b[2], bbase + 2 * bnstep);
        ldsm4(b[3], bbase + 3 * bnstep);
        #pragma unroll
        for (int mt = 0; mt < 2; ++mt)
            #pragma unroll
            for (int j = 0; j < 8; ++j)
                mma16816(c[mt][j], a[mt], &b[j >> 1][(j & 1) * 2]);
        abase += 32;
        bbase += 32;
    }
}

// ---------------------------------------------------------------- launch 1: hist
__global__ void hist_kernel(const int* __restrict__ dst) {
    const int base = (blockIdx.x * blockDim.x + threadIdx.x) * 4;
    if (base + 3 < N_EDGES) {
        const int4 d = *reinterpret_cast<const int4*>(dst + base);
        atomicAdd(&g_deg[d.x], 1);
        atomicAdd(&g_deg[d.y], 1);
        atomicAdd(&g_deg[d.z], 1);
        atomicAdd(&g_deg[d.w], 1);
    } else {
        for (int e = base; e < N_EDGES; ++e) atomicAdd(&g_deg[dst[e]], 1);
    }
}

// ---------------------------------------------------------------- launch 2:
// block 0 (256 thr): exclusive scan g_deg -> g_off; blocks 1..NNT: node1 P/Q
__global__ __launch_bounds__(256)
void scannode_kernel(const float* __restrict__ h,
                     const float* __restrict__ W1,
                     const float* __restrict__ b1) {
    __shared__ int part[256];
    extern __shared__ char smbuf[];

    if (blockIdx.x == 0) {
        const int t = threadIdx.x;
        const int start = t * 196;
        const int end   = (start + 196 < N_NODES) ? start + 196 : N_NODES;
        int s = 0;
        for (int i = start; i < end; ++i) s += g_deg[i];
        part[t] = s;
        __syncthreads();
        for (int o = 1; o < 256; o <<= 1) {
            int v = (t >= o) ? part[t - o] : 0;
            __syncthreads();
            part[t] += v;
            __syncthreads();
        }
        int run = (t == 0) ? 0 : part[t - 1];
        for (int i = start; i < end; ++i) {
            int d = g_deg[i];
            g_off[i] = run;
            run += d;
        }
        return;
    }

    // ---- node1 body (256 threads) ----
    const uint32_t sb = smem_u32(smbuf);
    float* b1s = reinterpret_cast<float*>(smbuf + NSM_B1S);

    const int t = threadIdx.x, l = t & 31, warp = t >> 5;
    const int wm = warp & 3, wn = warp >> 2;
    const int grow = t & 127, ghf = t >> 7;

    for (int i = t; i < 128 * 128; i += 256) {
        int k = i >> 7, n = i & 127;
        *reinterpret_cast<__half*>(smbuf + NSM_B0 + n * PB2 + k * 2) =
            __float2half_rn(W1[k * 128 + n]);
        *reinterpret_cast<__half*>(smbuf + NSM_B1 + n * PB2 + k * 2) =
            __float2half_rn(W1[(k + 128) * 128 + n]);
    }
    if (t < 128) b1s[t] = b1[t];

    const uint32_t aoff = ((l & 7) + 8 * ((l >> 3) & 1)) * PB2 + (l >> 4) * 16;
    const uint32_t boff = ((l & 7) + 8 * (l >> 4)) * PB2 + ((l >> 3) & 1) * 16;
    const uint32_t aX  = sb + NSM_X + 32 * wm * PB2 + aoff;
    const uint32_t bB0 = sb + NSM_B0 + 64 * wn * PB2 + boff;
    const uint32_t bB1 = sb + NSM_B1 + 64 * wn * PB2 + boff;
    const int rbase = 32 * wm + (l >> 2);
    const int cbase = 64 * wn + 2 * (l & 3);

    const int node = (blockIdx.x - 1) * 128 + grow;
    const int nc = node < N_NODES ? node : N_NODES - 1;

    {
        const float4* ps = reinterpret_cast<const float4*>(
            h + (size_t)nc * 128 + ghf * 64);
        char* xr = smbuf + NSM_X + grow * PB2 + ghf * 128;
        #pragma unroll
        for (int q = 0; q < 16; ++q) {
            float4 v = ps[q];
            *reinterpret_cast<uint2*>(xr + q * 8) =
                make_uint2(h2bits(v.x, v.y), h2bits(v.z, v.w));
        }
    }
    __syncthreads();

    #pragma unroll
    for (int pass = 0; pass < 2; ++pass) {
        float c[2][8][4];
        #pragma unroll
        for (int mt = 0; mt < 2; ++mt)
            #pragma unroll
            for (int j = 0; j < 8; ++j)
                #pragma unroll
                for (int i = 0; i < 4; ++i) c[mt][j][i] = 0.f;
        gemm_pass42<8>(c, aX, 16 * PB2, pass ? bB1 : bB0, 16 * PB2);
        #pragma unroll
        for (int mt = 0; mt < 2; ++mt)
            #pragma unroll
            for (int j = 0; j < 8; ++j) {
                const int col = cbase + 8 * j;
                const float bb0 = pass ? 0.f : b1s[col];
                const float bb1 = pass ? 0.f : b1s[col + 1];
                #pragma unroll
                for (int rh = 0; rh < 2; ++rh) {
                    const int row = rbase + 16 * mt + 8 * rh;
                    *reinterpret_cast<uint32_t*>(
                        smbuf + NSM_OUT + row * PB2 + col * 2) =
                        h2bits(c[mt][j][2 * rh] + bb0, c[mt][j][2 * rh + 1] + bb1);
                }
            }
        __syncthreads();
        if (node < N_NODES) {
            const uint4* os = reinterpret_cast<const uint4*>(
                smbuf + NSM_OUT + grow * PB2 + ghf * 128);
            uint4* po = reinterpret_cast<uint4*>(
                g_pq + (size_t)node * 256 + pass * 128 + ghf * 64);
            #pragma unroll
            for (int q = 0; q < 8; ++q) po[q] = os[q];
        }
        __syncthreads();
    }
}

// ---------------------------------------------------------------- launch 3: fill
__global__ void fill_kernel(const int* __restrict__ dst) {
    const int base = (blockIdx.x * blockDim.x + threadIdx.x) * 4;
    if (base + 3 < N_EDGES) {
        const int4 d = *reinterpret_cast<const int4*>(dst + base);
        const int p0 = atomicAdd(&g_off[d.x], 1);
        const int p1 = atomicAdd(&g_off[d.y], 1);
        const int p2 = atomicAdd(&g_off[d.z], 1);
        const int p3 = atomicAdd(&g_off[d.w], 1);
        g_eidx[p0] = base;
        g_eidx[p1] = base + 1;
        g_eidx[p2] = base + 2;
        g_eidx[p3] = base + 3;
    } else {
        for (int e = base; e < N_EDGES; ++e) {
            int p = atomicAdd(&g_off[dst[e]], 1);
            g_eidx[p] = e;
        }
    }
}

// ---------------------------------------------------------------- launch 4: edge (PROFILED)
__global__ __launch_bounds__(512, 2)
void edge_mma_kernel(const int*   __restrict__ src,
                     const int*   __restrict__ dst,
                     const float* __restrict__ ea,
                     const float* __restrict__ W1) {
    extern __shared__ char smbuf[];
    const uint32_t sb = smem_u32(smbuf);
    int* sidx  = reinterpret_cast<int*>(smbuf + SM_SIDX);
    int* didx  = reinterpret_cast<int*>(smbuf + SM_DIDX);
    int* eidxs = reinterpret_cast<int*>(smbuf + SM_EIDX);

    const int t = threadIdx.x, l = t & 31, warp = t >> 5;
    const int wm = warp & 3, wn = warp >> 2;       // 4x4 warp grid (E1 MMA)

    // ---- stage W1c^T (fp16) ----
    for (int i = t; i < 16 * 128; i += 512) {
        int k = i >> 7, n = i & 127;
        *reinterpret_cast<__half*>(smbuf + SM_W1C + n * PBEA + k * 2) =
            __float2half_rn(W1[(k + 256) * 128 + n]);
    }

    const uint32_t aoff48 = ((l & 7) + 8 * ((l >> 3) & 1)) * PBEA + (l >> 4) * 16;
    const uint32_t boff48 = ((l & 7) + 8 * (l >> 4)) * PBEA + ((l >> 3) & 1) * 16;
    const uint32_t aEA  = sb + SM_EA  + 64 * wm * PBEA + aoff48;   // 64 rows/warp
    const uint32_t bW1C = sb + SM_W1C + 32 * wn * PBEA + boff48;
    const int rbase = 64 * wm + (l >> 2);
    const int cbase = 32 * wn + 2 * (l & 3);

    // reduction lane map: 16 warps x 16 rows; each lane handles 4 consecutive cols
    const int rw  = warp;                 // 0..15 row group (16 rows each)
    const int c4  = l * 4;                // col base (0..124)

    __syncthreads();

    // preload W1c B-fragments (constant over tiles)
    uint32_t bE1[8];
    ldsm4(&bE1[0], bW1C);
    ldsm4(&bE1[4], bW1C + 16 * PBEA);

    for (int tile = blockIdx.x; tile < NT; tile += gridDim.x) {
        const int e0 = tile << 8;                  // 256 edges/tile
        __syncthreads();
        if (t < 256) {
            const int e = g_eidx[e0 + t];
            eidxs[t] = e;
            sidx[t]  = src[e];
            didx[t]  = dst[e];
        }
        __syncthreads();

        // ---- gather EA (2 thr/row) -> SMEM fp16 ----
        {
            const int row = t >> 1, q2 = t & 1;
            const float4* pe = reinterpret_cast<const float4*>(
                ea + (size_t)eidxs[row] * 16 + q2 * 8);
            char* eb = smbuf + SM_EA + row * PBEA + q2 * 16;
            float4 v0 = pe[0], v1 = pe[1];
            *reinterpret_cast<uint4*>(eb) =
                make_uint4(h2bits(v0.x, v0.y), h2bits(v0.z, v0.w),
                           h2bits(v1.x, v1.y), h2bits(v1.z, v1.w));
        }
        __syncthreads();

        // ---- E1 = ea @ W1c^T (K=16), fp16 -> SM_HDN ----
        #pragma unroll
        for (int mt = 0; mt < 4; ++mt) {
            uint32_t a[4];
            ldsm4(a, aEA + mt * 16 * PBEA);
            float c[4][4];
            #pragma unroll
            for (int j = 0; j < 4; ++j)
                #pragma unroll
                for (int i = 0; i < 4; ++i) c[j][i] = 0.f;
            #pragma unroll
            for (int j = 0; j < 4; ++j)
                mma16816(c[j], a, &bE1[(j >> 1) * 4 + (j & 1) * 2]);
            #pragma unroll
            for (int j = 0; j < 4; ++j) {
                const int col = cbase + 8 * j;
                #pragma unroll
                for (int rh = 0; rh < 2; ++rh) {
                    const int row = rbase + 16 * mt + 8 * rh;
                    *reinterpret_cast<uint32_t*>(
                        smbuf + SM_HDN + row * PB2 + col * 2) =
                        h2bits(c[j][2 * rh], c[j][2 * rh + 1]);
                }
            }
        }
        __syncthreads();

        // ---- fused gelu(P[src]+Q[dst]+E1) + segmented reduction -> g_hsum ----
        {
            const char* pqb = reinterpret_cast<const char*>(g_pq);
            float a0 = 0.f, a1 = 0.f, a2 = 0.f, a3 = 0.f;
            #pragma unroll
            for (int r = 0; r < 16; ++r) {
                const int row = rw * 16 + r;
                const int sN = sidx[row], dN = didx[row];
                const uint2 e1 = *reinterpret_cast<const uint2*>(
                    smbuf + SM_HDN + row * PB2 + c4 * 2);
                const uint2 pv = *reinterpret_cast<const uint2*>(
                    pqb + (uint32_t)sN * 512u + (uint32_t)(c4 * 2));
                const uint2 qv = *reinterpret_cast<const uint2*>(
                    pqb + (uint32_t)dN * 512u + 256u + (uint32_t)(c4 * 2));
                const __half2 s0 = __hadd2(
                    __hadd2(*reinterpret_cast<const __half2*>(&pv.x),
                            *reinterpret_cast<const __half2*>(&qv.x)),
                    *reinterpret_cast<const __half2*>(&e1.x));
                const __half2 s1 = __hadd2(
                    __hadd2(*reinterpret_cast<const __half2*>(&pv.y),
                            *reinterpret_cast<const __half2*>(&qv.y)),
                    *reinterpret_cast<const __half2*>(&e1.y));
                const float2 f0 = __half22float2(s0);
                const float2 f1 = __half22float2(s1);
                a0 += gelu_fast(f0.x);
                a1 += gelu_fast(f0.y);
                a2 += gelu_fast(f1.x);
                a3 += gelu_fast(f1.y);
                const bool flush = (r == 15) || (dN != didx[row + 1]);
                if (flush) {
                    asm volatile("red.global.add.v4.f32 [%0], {%1,%2,%3,%4};"
                                 :: "l"(g_hsum + (size_t)dN * 128 + c4),
                                    "f"(a0), "f"(a1), "f"(a2), "f"(a3)
                                 : "memory");
                    a0 = a1 = a2 = a3 = 0.f;
                }
            }
        }
    }
}

// ---------------------------------------------------------------- launch 5: node2 (+cleanup)
// out = LayerNorm(h + hsum @ W2 + deg*b2); then re-zero own rows of hsum/deg
__global__ __launch_bounds__(256, 1)
void node2_kernel(const float* __restrict__ h,
                  const float* __restrict__ W2,
                  const float* __restrict__ b2,
                  const float* __restrict__ gamma,
                  const float* __restrict__ beta,
                  float* __restrict__ out) {
    extern __shared__ char smbuf[];
    const uint32_t sb = smem_u32(smbuf);
    float* b2s = reinterpret_cast<float*>(smbuf + N2_B2);
    float* gms = reinterpret_cast<float*>(smbuf + N2_GAM);
    float* bts = reinterpret_cast<float*>(smbuf + N2_BET);
    int*   dgs = reinterpret_cast<int*>(smbuf + N2_DEG);
    float* outs = reinterpret_cast<float*>(smbuf + N2_OUT);

    const int t = threadIdx.x, l = t & 31, warp = t >> 5;
    const int wm = warp & 3, wn = warp >> 2;
    const int grow = t & 127, ghf = t >> 7;

    for (int i = t; i < 128 * 128; i += 256) {
        int k = i >> 7, n = i & 127;
        *reinterpret_cast<__half*>(smbuf + N2_W2 + n * PB2 + k * 2) =
            __float2half_rn(W2[i]);
    }
    if (t < 128) { b2s[t] = b2[t]; gms[t] = gamma[t]; bts[t] = beta[t]; }

    const int node = blockIdx.x * 128 + grow;
    const int nc = node < N_NODES ? node : N_NODES - 1;
    if (t >= 128 && t < 256) {
        int nn = blockIdx.x * 128 + (t - 128);
        dgs[t - 128] = (nn < N_NODES) ? g_deg[nn] : 0;
    }

    {
        const float4* ps = reinterpret_cast<const float4*>(
            g_hsum + (size_t)nc * 128 + ghf * 64);
        char* xr = smbuf + N2_X + grow * PB2 + ghf * 128;
        #pragma unroll
        for (int q = 0; q < 16; ++q) {
            float4 v = ps[q];
            *reinterpret_cast<uint2*>(xr + q * 8) =
                make_uint2(h2bits(v.x, v.y), h2bits(v.z, v.w));
        }
    }
    __syncthreads();

    const uint32_t aoff = ((l & 7) + 8 * ((l >> 3) & 1)) * PB2 + (l >> 4) * 16;
    const uint32_t boff = ((l & 7) + 8 * (l >> 4)) * PB2 + ((l >> 3) & 1) * 16;
    const uint32_t aX = sb + N2_X + 32 * wm * PB2 + aoff;
    const uint32_t bW = sb + N2_W2 + 64 * wn * PB2 + boff;
    const int rbase = 32 * wm + (l >> 2);
    const int cbase = 64 * wn + 2 * (l & 3);

    float c[2][8][4];
    #pragma unroll
    for (int mt = 0; mt < 2; ++mt)
        #pragma unroll
        for (int j = 0; j < 8; ++j)
            #pragma unroll
            for (int i = 0; i < 4; ++i) c[mt][j][i] = 0.f;
    gemm_pass42<8>(c, aX, 16 * PB2, bW, 16 * PB2);

    #pragma unroll
    for (int mt = 0; mt < 2; ++mt)
        #pragma unroll
        for (int j = 0; j < 8; ++j) {
            const int col = cbase + 8 * j;
            const float bb0 = b2s[col], bb1 = b2s[col + 1];
            #pragma unroll
            for (int rh = 0; rh < 2; ++rh) {
                const int row = rbase + 16 * mt + 8 * rh;
                const float dg = (float)dgs[row];
                outs[row * 132 + col]     = c[mt][j][2 * rh] + dg * bb0;
                outs[row * 132 + col + 1] = c[mt][j][2 * rh + 1] + dg * bb1;
            }
        }
    __syncthreads();

    for (int r = 0; r < 16; ++r) {
        const int row = warp * 16 + r;
        const int nn = blockIdx.x * 128 + row;
        if (nn >= N_NODES) break;
        const float4 hv = reinterpret_cast<const float4*>(h)[(size_t)nn * 32 + l];
        const float4 av = *reinterpret_cast<const float4*>(outs + row * 132 + l * 4);
        float4 x;
        x.x = hv.x + av.x; x.y = hv.y + av.y;
        x.z = hv.z + av.z; x.w = hv.w + av.w;
        float s = x.x + x.y + x.z + x.w;
        #pragma unroll
        for (int o = 16; o > 0; o >>= 1) s += __shfl_xor_sync(0xffffffffu, s, o);
        const float mu = s * (1.0f / 128.0f);
        const float dx = x.x - mu, dy = x.y - mu, dz = x.z - mu, dw = x.w - mu;
        float q = dx * dx + dy * dy + dz * dz + dw * dw;
        #pragma unroll
        for (int o = 16; o > 0; o >>= 1) q += __shfl_xor_sync(0xffffffffu, q, o);
        const float inv = rsqrtf(q * (1.0f / 128.0f) + 1e-5f);
        float4 o4;
        o4.x = dx * inv * gms[l * 4 + 0] + bts[l * 4 + 0];
        o4.y = dy * inv * gms[l * 4 + 1] + bts[l * 4 + 1];
        o4.z = dz * inv * gms[l * 4 + 2] + bts[l * 4 + 2];
        o4.w = dw * inv * gms[l * 4 + 3] + bts[l * 4 + 3];
        reinterpret_cast<float4*>(out)[(size_t)nn * 32 + l] = o4;
    }

    // ---- cleanup: restore zero-state of this block's hsum rows + deg ----
    {
        const int row0 = blockIdx.x * 128;
        float4* hz = reinterpret_cast<float4*>(g_hsum + (size_t)row0 * 128);
        for (int i = t; i < 128 * 32; i += 256) {
            const int rr = row0 + (i >> 5);
            if (rr < N_NODES) hz[i] = make_float4(0.f, 0.f, 0.f, 0.f);
        }
        if (t < 128) {
            const int nn = row0 + t;
            if (nn < N_NODES) g_deg[nn] = 0;
        }
    }
}

// ----------------------------------------------------------------
extern "C" void kernel_launch(void* const* d_in, const int* in_sizes, int n_in,
                              void* d_out, int out_size) {
    const float* h     = (const float*)d_in[0];
    const int*   src   = (const int*)  d_in[1];
    const int*   dst   = (const int*)  d_in[2];
    const float* ea    = (const float*)d_in[3];
    const float* W1    = (const float*)d_in[4];
    const float* b1    = (const float*)d_in[5];
    const float* W2    = (const float*)d_in[6];
    const float* b2    = (const float*)d_in[7];
    const float* gamma = (const float*)d_in[8];
    const float* beta  = (const float*)d_in[9];
    float*       out   = (float*)d_out;

    static int sm_count = []() {
        int dev = 0, c = 148;
        cudaGetDevice(&dev);
        cudaDeviceGetAttribute(&c, cudaDevAttrMultiProcessorCount, dev);
        return c;
    }();
    static bool attr_ok = []() {
        cudaFuncSetAttribute(edge_mma_kernel,
                             cudaFuncAttributeMaxDynamicSharedMemorySize, SMEM_E);
        cudaFuncSetAttribute(scannode_kernel,
                             cudaFuncAttributeMaxDynamicSharedMemorySize, SMEM_N);
        cudaFuncSetAttribute(node2_kernel,
                             cudaFuncAttributeMaxDynamicSharedMemorySize, SMEM_N2);
        return true;
    }();
    (void)attr_ok;

    hist_kernel<<<(N_EDGES / 4 + 255) / 256, 256>>>(dst);              // 1
    scannode_kernel<<<1 + NNT, 256, SMEM_N>>>(h, W1, b1);              // 2
    fill_kernel<<<(N_EDGES / 4 + 255) / 256, 256>>>(dst);              // 3
    edge_mma_kernel<<<2 * sm_count, 512, SMEM_E>>>(src, dst, ea, W1);  // 4 <- profiled
    node2_kernel<<<NNT, 256, SMEM_N2>>>(h, W2, b2, gamma, beta, out);  // 5
}

// round 14
// speedup vs baseline: 1.4306x; 1.0181x over previous
#include <cuda_runtime.h>
#include <cuda_fp16.h>
#include <math.h>
#include <stdint.h>

#define N_NODES 50000
#define N_EDGES 1600000
#define NT      12500       // edge tiles of 128
#define NNT     391         // node tiles of 128

// ---- pitches
#define PB2  272    // fp16 [.][k=128 pad] (ldmatrix layout / E1 pitch)
#define PBEA 48     // fp16 [.][k=16 pad]

// ---- edge-kernel SMEM offsets (bytes), 128-edge tiles (4 CTAs/SM)
#define SM_HDN   0           // 128*272 = 34816 (E1 fp16)
#define SM_EA    34816       // 6144
#define SM_W1C   40960       // 6144
#define SM_SIDX  47104       // 512
#define SM_DIDX  47616       // 512
#define SM_EIDX  48128       // 512
#define SMEM_E   48640       // x4 = 194560 <= 227KB

// ---- node1 (P/Q) SMEM offsets (dynamic smem of scannode kernel)
#define NSM_X   0
#define NSM_B0  34816
#define NSM_B1  69632
#define NSM_OUT 104448
#define NSM_B1S 139264
#define SMEM_N  139776

// ---- node2 (GEMM2+LN) SMEM offsets
#define N2_W2   0
#define N2_X    34816
#define N2_OUT  69632        // f32 [128][132]
#define N2_B2   137216
#define N2_GAM  137728
#define N2_BET  138240
#define N2_DEG  138752
#define SMEM_N2 139264

// Invariant: g_hsum and g_deg are ZERO at entry of every kernel_launch call
// (zero-initialized at load; node2_kernel re-zeroes its rows at the end).
__device__ float   g_hsum[(size_t)N_NODES * 128];
__device__ __half  g_pq [(size_t)N_NODES * 256];  // [0:128]=P=h@W1a+b1, [128:256]=Q=h@W1b
__device__ int     g_deg [N_NODES];
__device__ int     g_off [N_NODES];
__device__ int     g_eidx[N_EDGES];

// ---------------------------------------------------------------- helpers
__device__ __forceinline__ uint32_t smem_u32(const void* p) {
    uint32_t a;
    asm("{ .reg .u64 t; cvta.to.shared.u64 t, %1; cvt.u32.u64 %0, t; }"
        : "=r"(a) : "l"(p));
    return a;
}
__device__ __forceinline__ void ldsm4(uint32_t* r, uint32_t addr) {
    asm volatile("ldmatrix.sync.aligned.m8n8.x4.shared.b16 {%0,%1,%2,%3}, [%4];"
                 : "=r"(r[0]), "=r"(r[1]), "=r"(r[2]), "=r"(r[3]) : "r"(addr));
}
__device__ __forceinline__ void mma16816(float* c, const uint32_t* a,
                                         const uint32_t* b) {
    asm volatile("mma.sync.aligned.m16n8k16.row.col.f32.f16.f16.f32 "
                 "{%0,%1,%2,%3}, {%4,%5,%6,%7}, {%8,%9}, {%0,%1,%2,%3};"
                 : "+f"(c[0]), "+f"(c[1]), "+f"(c[2]), "+f"(c[3])
                 : "r"(a[0]), "r"(a[1]), "r"(a[2]), "r"(a[3]),
                   "r"(b[0]), "r"(b[1]));
}
__device__ __forceinline__ uint32_t h2bits(float a, float b) {
    __half2 h = __floats2half2_rn(a, b);
    return *reinterpret_cast<uint32_t*>(&h);
}
// exact-GELU via A&S 7.1.26 erf (abs err 1.5e-7)
__device__ __forceinline__ float gelu_fast(float v) {
    const float x = v * 0.70710678118654752440f;
    const float s = fabsf(x);
    float t;
    asm("rcp.approx.f32 %0, %1;" : "=f"(t)
        : "f"(fmaf(0.3275911f, s, 1.0f)));
    const float e = __expf(-s * s);
    float p = fmaf(t, 1.061405429f, -1.453152027f);
    p = fmaf(t, p, 1.421413741f);
    p = fmaf(t, p, -0.284496736f);
    p = fmaf(t, p, 0.254829592f);
    p = p * t;
    const float erfs = fmaf(-p, e, 1.0f);
    return 0.5f * v * (1.0f + copysignf(erfs, x));
}

template <int NCH>
__device__ __forceinline__ void gemm_pass42(float (&c)[2][8][4],
                                            uint32_t abase, uint32_t amstep,
                                            uint32_t bbase, uint32_t bnstep) {
    #pragma unroll
    for (int kc = 0; kc < NCH; ++kc) {
        uint32_t a[2][4], b[4][4];
        ldsm4(a[0], abase);
        ldsm4(a[1], abase + amstep);
        ldsm4(b[0], bbase);
        ldsm4(b[1], bbase + bnstep);
        ldsm4(b[2], bbase + 2 * bnstep);
        ldsm4(b[3], bbase + 3 * bnstep);
        #pragma unroll
        for (int mt = 0; mt < 2; ++mt)
            #pragma unroll
            for (int j = 0; j < 8; ++j)
                mma16816(c[mt][j], a[mt], &b[j >> 1][(j & 1) * 2]);
        abase += 32;
        bbase += 32;
    }
}

// ---------------------------------------------------------------- launch 1: hist
__global__ void hist_kernel(const int* __restrict__ dst) {
    const int base = (blockIdx.x * blockDim.x + threadIdx.x) * 4;
    if (base + 3 < N_EDGES) {
        const int4 d = *reinterpret_cast<const int4*>(dst + base);
        atomicAdd(&g_deg[d.x], 1);
        atomicAdd(&g_deg[d.y], 1);
        atomicAdd(&g_deg[d.z], 1);
        atomicAdd(&g_deg[d.w], 1);
    } else {
        for (int e = base; e < N_EDGES; ++e) atomicAdd(&g_deg[dst[e]], 1);
    }
}

// ---------------------------------------------------------------- launch 2:
// block 0 (256 thr): exclusive scan g_deg -> g_off; blocks 1..NNT: node1 P/Q
__global__ __launch_bounds__(256)
void scannode_kernel(const float* __restrict__ h,
                     const float* __restrict__ W1,
                     const float* __restrict__ b1) {
    __shared__ int part[256];
    extern __shared__ char smbuf[];

    if (blockIdx.x == 0) {
        const int t = threadIdx.x;
        const int start = t * 196;
        const int end   = (start + 196 < N_NODES) ? start + 196 : N_NODES;
        int s = 0;
        for (int i = start; i < end; ++i) s += g_deg[i];
        part[t] = s;
        __syncthreads();
        for (int o = 1; o < 256; o <<= 1) {
            int v = (t >= o) ? part[t - o] : 0;
            __syncthreads();
            part[t] += v;
            __syncthreads();
        }
        int run = (t == 0) ? 0 : part[t - 1];
        for (int i = start; i < end; ++i) {
            int d = g_deg[i];
            g_off[i] = run;
            run += d;
        }
        return;
    }

    // ---- node1 body (256 threads) ----
    const uint32_t sb = smem_u32(smbuf);
    float* b1s = reinterpret_cast<float*>(smbuf + NSM_B1S);

    const int t = threadIdx.x, l = t & 31, warp = t >> 5;
    const int wm = warp & 3, wn = warp >> 2;
    const int grow = t & 127, ghf = t >> 7;

    for (int i = t; i < 128 * 128; i += 256) {
        int k = i >> 7, n = i & 127;
        *reinterpret_cast<__half*>(smbuf + NSM_B0 + n * PB2 + k * 2) =
            __float2half_rn(W1[k * 128 + n]);
        *reinterpret_cast<__half*>(smbuf + NSM_B1 + n * PB2 + k * 2) =
            __float2half_rn(W1[(k + 128) * 128 + n]);
    }
    if (t < 128) b1s[t] = b1[t];

    const uint32_t aoff = ((l & 7) + 8 * ((l >> 3) & 1)) * PB2 + (l >> 4) * 16;
    const uint32_t boff = ((l & 7) + 8 * (l >> 4)) * PB2 + ((l >> 3) & 1) * 16;
    const uint32_t aX  = sb + NSM_X + 32 * wm * PB2 + aoff;
    const uint32_t bB0 = sb + NSM_B0 + 64 * wn * PB2 + boff;
    const uint32_t bB1 = sb + NSM_B1 + 64 * wn * PB2 + boff;
    const int rbase = 32 * wm + (l >> 2);
    const int cbase = 64 * wn + 2 * (l & 3);

    const int node = (blockIdx.x - 1) * 128 + grow;
    const int nc = node < N_NODES ? node : N_NODES - 1;

    {
        const float4* ps = reinterpret_cast<const float4*>(
            h + (size_t)nc * 128 + ghf * 64);
        char* xr = smbuf + NSM_X + grow * PB2 + ghf * 128;
        #pragma unroll
        for (int q = 0; q < 16; ++q) {
            float4 v = ps[q];
            *reinterpret_cast<uint2*>(xr + q * 8) =
                make_uint2(h2bits(v.x, v.y), h2bits(v.z, v.w));
        }
    }
    __syncthreads();

    #pragma unroll
    for (int pass = 0; pass < 2; ++pass) {
        float c[2][8][4];
        #pragma unroll
        for (int mt = 0; mt < 2; ++mt)
            #pragma unroll
            for (int j = 0; j < 8; ++j)
                #pragma unroll
                for (int i = 0; i < 4; ++i) c[mt][j][i] = 0.f;
        gemm_pass42<8>(c, aX, 16 * PB2, pass ? bB1 : bB0, 16 * PB2);
        #pragma unroll
        for (int mt = 0; mt < 2; ++mt)
            #pragma unroll
            for (int j = 0; j < 8; ++j) {
                const int col = cbase + 8 * j;
                const float bb0 = pass ? 0.f : b1s[col];
                const float bb1 = pass ? 0.f : b1s[col + 1];
                #pragma unroll
                for (int rh = 0; rh < 2; ++rh) {
                    const int row = rbase + 16 * mt + 8 * rh;
                    *reinterpret_cast<uint32_t*>(
                        smbuf + NSM_OUT + row * PB2 + col * 2) =
                        h2bits(c[mt][j][2 * rh] + bb0, c[mt][j][2 * rh + 1] + bb1);
                }
            }
        __syncthreads();
        if (node < N_NODES) {
            const uint4* os = reinterpret_cast<const uint4*>(
                smbuf + NSM_OUT + grow * PB2 + ghf * 128);
            uint4* po = reinterpret_cast<uint4*>(
                g_pq + (size_t)node * 256 + pass * 128 + ghf * 64);
            #pragma unroll
            for (int q = 0; q < 8; ++q) po[q] = os[q];
        }
        __syncthreads();
    }
}

// ---------------------------------------------------------------- launch 3: fill
__global__ void fill_kernel(const int* __restrict__ dst) {
    const int base = (blockIdx.x * blockDim.x + threadIdx.x) * 4;
    if (base + 3 < N_EDGES) {
        const int4 d = *reinterpret_cast<const int4*>(dst + base);
        const int p0 = atomicAdd(&g_off[d.x], 1);
        const int p1 = atomicAdd(&g_off[d.y], 1);
        const int p2 = atomicAdd(&g_off[d.z], 1);
        const int p3 = atomicAdd(&g_off[d.w], 1);
        g_eidx[p0] = base;
        g_eidx[p1] = base + 1;
        g_eidx[p2] = base + 2;
        g_eidx[p3] = base + 3;
    } else {
        for (int e = base; e < N_EDGES; ++e) {
            int p = atomicAdd(&g_off[dst[e]], 1);
            g_eidx[p] = e;
        }
    }
}

// ---------------------------------------------------------------- launch 4: edge (PROFILED)
// 128-edge tiles, 512 threads, 4 CTAs/SM (100% occupancy)
__global__ __launch_bounds__(512, 4)
void edge_mma_kernel(const int*   __restrict__ src,
                     const int*   __restrict__ dst,
                     const float* __restrict__ ea,
                     const float* __restrict__ W1) {
    extern __shared__ char smbuf[];
    const uint32_t sb = smem_u32(smbuf);
    int* sidx  = reinterpret_cast<int*>(smbuf + SM_SIDX);
    int* didx  = reinterpret_cast<int*>(smbuf + SM_DIDX);
    int* eidxs = reinterpret_cast<int*>(smbuf + SM_EIDX);

    const int t = threadIdx.x, l = t & 31, warp = t >> 5;
    const int wm = warp & 3, wn = warp >> 2;       // 4x4 warp grid (E1 MMA)

    // ---- stage W1c^T (fp16) ----
    for (int i = t; i < 16 * 128; i += 512) {
        int k = i >> 7, n = i & 127;
        *reinterpret_cast<__half*>(smbuf + SM_W1C + n * PBEA + k * 2) =
            __float2half_rn(W1[(k + 256) * 128 + n]);
    }

    const uint32_t aoff48 = ((l & 7) + 8 * ((l >> 3) & 1)) * PBEA + (l >> 4) * 16;
    const uint32_t boff48 = ((l & 7) + 8 * (l >> 4)) * PBEA + ((l >> 3) & 1) * 16;
    const uint32_t aEA  = sb + SM_EA  + 32 * wm * PBEA + aoff48;   // 32 rows/warp
    const uint32_t bW1C = sb + SM_W1C + 32 * wn * PBEA + boff48;
    const int rbase = 32 * wm + (l >> 2);
    const int cbase = 32 * wn + 2 * (l & 3);

    // reduction lane map: 16 warps x 8 rows; each lane handles 4 consecutive cols
    const int rw = warp;                  // 0..15 row group (8 rows each)
    const int c4 = l * 4;                 // col base (0..124)

    __syncthreads();

    for (int tile = blockIdx.x; tile < NT; tile += gridDim.x) {
        const int e0 = tile << 7;                  // 128 edges/tile
        __syncthreads();
        if (t < 128) {
            const int e = g_eidx[e0 + t];
            eidxs[t] = e;
            sidx[t]  = src[e];
            didx[t]  = dst[e];
        }
        __syncthreads();

        // ---- gather EA (4 thr/row) -> SMEM fp16 ----
        {
            const int row = t >> 2, q4 = t & 3;
            float4 v = reinterpret_cast<const float4*>(
                ea + (size_t)eidxs[row] * 16)[q4];
            *reinterpret_cast<uint2*>(smbuf + SM_EA + row * PBEA + q4 * 8) =
                make_uint2(h2bits(v.x, v.y), h2bits(v.z, v.w));
        }
        __syncthreads();

        // ---- E1 = ea @ W1c^T (K=16), fp16 -> SM_HDN ----
        {
            uint32_t bE1[8];
            ldsm4(&bE1[0], bW1C);
            ldsm4(&bE1[4], bW1C + 16 * PBEA);
            #pragma unroll
            for (int mt = 0; mt < 2; ++mt) {
                uint32_t a[4];
                ldsm4(a, aEA + mt * 16 * PBEA);
                float c[4][4];
                #pragma unroll
                for (int j = 0; j < 4; ++j)
                    #pragma unroll
                    for (int i = 0; i < 4; ++i) c[j][i] = 0.f;
                #pragma unroll
                for (int j = 0; j < 4; ++j)
                    mma16816(c[j], a, &bE1[(j >> 1) * 4 + (j & 1) * 2]);
                #pragma unroll
                for (int j = 0; j < 4; ++j) {
                    const int col = cbase + 8 * j;
                    #pragma unroll
                    for (int rh = 0; rh < 2; ++rh) {
                        const int row = rbase + 16 * mt + 8 * rh;
                        *reinterpret_cast<uint32_t*>(
                            smbuf + SM_HDN + row * PB2 + col * 2) =
                            h2bits(c[j][2 * rh], c[j][2 * rh + 1]);
                    }
                }
            }
        }
        __syncthreads();

        // ---- fused gelu(P[src]+Q[dst]+E1) + segmented reduction -> g_hsum ----
        {
            const char* pqb = reinterpret_cast<const char*>(g_pq);
            float a0 = 0.f, a1 = 0.f, a2 = 0.f, a3 = 0.f;
            #pragma unroll
            for (int r = 0; r < 8; ++r) {
                const int row = rw * 8 + r;
                const int sN = sidx[row], dN = didx[row];
                const uint2 e1 = *reinterpret_cast<const uint2*>(
                    smbuf + SM_HDN + row * PB2 + c4 * 2);
                const uint2 pv = *reinterpret_cast<const uint2*>(
                    pqb + (uint32_t)sN * 512u + (uint32_t)(c4 * 2));
                const uint2 qv = *reinterpret_cast<const uint2*>(
                    pqb + (uint32_t)dN * 512u + 256u + (uint32_t)(c4 * 2));
                const __half2 s0 = __hadd2(
                    __hadd2(*reinterpret_cast<const __half2*>(&pv.x),
                            *reinterpret_cast<const __half2*>(&qv.x)),
                    *reinterpret_cast<const __half2*>(&e1.x));
                const __half2 s1 = __hadd2(
                    __hadd2(*reinterpret_cast<const __half2*>(&pv.y),
                            *reinterpret_cast<const __half2*>(&qv.y)),
                    *reinterpret_cast<const __half2*>(&e1.y));
                const float2 f0 = __half22float2(s0);
                const float2 f1 = __half22float2(s1);
                a0 += gelu_fast(f0.x);
                a1 += gelu_fast(f0.y);
                a2 += gelu_fast(f1.x);
                a3 += gelu_fast(f1.y);
                const bool flush = (r == 7) || (dN != didx[row + 1]);
                if (flush) {
                    asm volatile("red.global.add.v4.f32 [%0], {%1,%2,%3,%4};"
                                 :: "l"(g_hsum + (size_t)dN * 128 + c4),
                                    "f"(a0), "f"(a1), "f"(a2), "f"(a3)
                                 : "memory");
                    a0 = a1 = a2 = a3 = 0.f;
                }
            }
        }
    }
}

// ---------------------------------------------------------------- launch 5: node2 (+cleanup)
// out = LayerNorm(h + hsum @ W2 + deg*b2); then re-zero own rows of hsum/deg
__global__ __launch_bounds__(256, 1)
void node2_kernel(const float* __restrict__ h,
                  const float* __restrict__ W2,
                  const float* __restrict__ b2,
                  const float* __restrict__ gamma,
                  const float* __restrict__ beta,
                  float* __restrict__ out) {
    extern __shared__ char smbuf[];
    const uint32_t sb = smem_u32(smbuf);
    float* b2s = reinterpret_cast<float*>(smbuf + N2_B2);
    float* gms = reinterpret_cast<float*>(smbuf + N2_GAM);
    float* bts = reinterpret_cast<float*>(smbuf + N2_BET);
    int*   dgs = reinterpret_cast<int*>(smbuf + N2_DEG);
    float* outs = reinterpret_cast<float*>(smbuf + N2_OUT);

    const int t = threadIdx.x, l = t & 31, warp = t >> 5;
    const int wm = warp & 3, wn = warp >> 2;
    const int grow = t & 127, ghf = t >> 7;

    for (int i = t; i < 128 * 128; i += 256) {
        int k = i >> 7, n = i & 127;
        *reinterpret_cast<__half*>(smbuf + N2_W2 + n * PB2 + k * 2) =
            __float2half_rn(W2[i]);
    }
    if (t < 128) { b2s[t] = b2[t]; gms[t] = gamma[t]; bts[t] = beta[t]; }

    const int node = blockIdx.x * 128 + grow;
    const int nc = node < N_NODES ? node : N_NODES - 1;
    if (t >= 128 && t < 256) {
        int nn = blockIdx.x * 128 + (t - 128);
        dgs[t - 128] = (nn < N_NODES) ? g_deg[nn] : 0;
    }

    {
        const float4* ps = reinterpret_cast<const float4*>(
            g_hsum + (size_t)nc * 128 + ghf * 64);
        char* xr = smbuf + N2_X + grow * PB2 + ghf * 128;
        #pragma unroll
        for (int q = 0; q < 16; ++q) {
            float4 v = ps[q];
            *reinterpret_cast<uint2*>(xr + q * 8) =
                make_uint2(h2bits(v.x, v.y), h2bits(v.z, v.w));
        }
    }
    __syncthreads();

    const uint32_t aoff = ((l & 7) + 8 * ((l >> 3) & 1)) * PB2 + (l >> 4) * 16;
    const uint32_t boff = ((l & 7) + 8 * (l >> 4)) * PB2 + ((l >> 3) & 1) * 16;
    const uint32_t aX = sb + N2_X + 32 * wm * PB2 + aoff;
    const uint32_t bW = sb + N2_W2 + 64 * wn * PB2 + boff;
    const int rbase = 32 * wm + (l >> 2);
    const int cbase = 64 * wn + 2 * (l & 3);

    float c[2][8][4];
    #pragma unroll
    for (int mt = 0; mt < 2; ++mt)
        #pragma unroll
        for (int j = 0; j < 8; ++j)
            #pragma unroll
            for (int i = 0; i < 4; ++i) c[mt][j][i] = 0.f;
    gemm_pass42<8>(c, aX, 16 * PB2, bW, 16 * PB2);

    #pragma unroll
    for (int mt = 0; mt < 2; ++mt)
        #pragma unroll
        for (int j = 0; j < 8; ++j) {
            const int col = cbase + 8 * j;
            const float bb0 = b2s[col], bb1 = b2s[col + 1];
            #pragma unroll
            for (int rh = 0; rh < 2; ++rh) {
                const int row = rbase + 16 * mt + 8 * rh;
                const float dg = (float)dgs[row];
                outs[row * 132 + col]     = c[mt][j][2 * rh] + dg * bb0;
                outs[row * 132 + col + 1] = c[mt][j][2 * rh + 1] + dg * bb1;
            }
        }
    __syncthreads();

    for (int r = 0; r < 16; ++r) {
        const int row = warp * 16 + r;
        const int nn = blockIdx.x * 128 + row;
        if (nn >= N_NODES) break;
        const float4 hv = reinterpret_cast<const float4*>(h)[(size_t)nn * 32 + l];
        const float4 av = *reinterpret_cast<const float4*>(outs + row * 132 + l * 4);
        float4 x;
        x.x = hv.x + av.x; x.y = hv.y + av.y;
        x.z = hv.z + av.z; x.w = hv.w + av.w;
        float s = x.x + x.y + x.z + x.w;
        #pragma unroll
        for (int o = 16; o > 0; o >>= 1) s += __shfl_xor_sync(0xffffffffu, s, o);
        const float mu = s * (1.0f / 128.0f);
        const float dx = x.x - mu, dy = x.y - mu, dz = x.z - mu, dw = x.w - mu;
        float q = dx * dx + dy * dy + dz * dz + dw * dw;
        #pragma unroll
        for (int o = 16; o > 0; o >>= 1) q += __shfl_xor_sync(0xffffffffu, q, o);
        const float inv = rsqrtf(q * (1.0f / 128.0f) + 1e-5f);
        float4 o4;
        o4.x = dx * inv * gms[l * 4 + 0] + bts[l * 4 + 0];
        o4.y = dy * inv * gms[l * 4 + 1] + bts[l * 4 + 1];
        o4.z = dz * inv * gms[l * 4 + 2] + bts[l * 4 + 2];
        o4.w = dw * inv * gms[l * 4 + 3] + bts[l * 4 + 3];
        reinterpret_cast<float4*>(out)[(size_t)nn * 32 + l] = o4;
    }

    // ---- cleanup: restore zero-state of this block's hsum rows + deg ----
    {
        const int row0 = blockIdx.x * 128;
        float4* hz = reinterpret_cast<float4*>(g_hsum + (size_t)row0 * 128);
        for (int i = t; i < 128 * 32; i += 256) {
            const int rr = row0 + (i >> 5);
            if (rr < N_NODES) hz[i] = make_float4(0.f, 0.f, 0.f, 0.f);
        }
        if (t < 128) {
            const int nn = row0 + t;
            if (nn < N_NODES) g_deg[nn] = 0;
        }
    }
}

// ----------------------------------------------------------------
extern "C" void kernel_launch(void* const* d_in, const int* in_sizes, int n_in,
                              void* d_out, int out_size) {
    const float* h     = (const float*)d_in[0];
    const int*   src   = (const int*)  d_in[1];
    const int*   dst   = (const int*)  d_in[2];
    const float* ea    = (const float*)d_in[3];
    const float* W1    = (const float*)d_in[4];
    const float* b1    = (const float*)d_in[5];
    const float* W2    = (const float*)d_in[6];
    const float* b2    = (const float*)d_in[7];
    const float* gamma = (const float*)d_in[8];
    const float* beta  = (const float*)d_in[9];
    float*       out   = (float*)d_out;

    static int sm_count = []() {
        int dev = 0, c = 148;
        cudaGetDevice(&dev);
        cudaDeviceGetAttribute(&c, cudaDevAttrMultiProcessorCount, dev);
        return c;
    }();
    static bool attr_ok = []() {
        cudaFuncSetAttribute(edge_mma_kernel,
                             cudaFuncAttributeMaxDynamicSharedMemorySize, SMEM_E);
        cudaFuncSetAttribute(scannode_kernel,
                             cudaFuncAttributeMaxDynamicSharedMemorySize, SMEM_N);
        cudaFuncSetAttribute(node2_kernel,
                             cudaFuncAttributeMaxDynamicSharedMemorySize, SMEM_N2);
        return true;
    }();
    (void)attr_ok;

    hist_kernel<<<(N_EDGES / 4 + 255) / 256, 256>>>(dst);              // 1
    scannode_kernel<<<1 + NNT, 256, SMEM_N>>>(h, W1, b1);              // 2
    fill_kernel<<<(N_EDGES / 4 + 255) / 256, 256>>>(dst);              // 3
    edge_mma_kernel<<<4 * sm_count, 512, SMEM_E>>>(src, dst, ea, W1);  // 4 <- profiled
    node2_kernel<<<NNT, 256, SMEM_N2>>>(h, W2, b2, gamma, beta, out);  // 5
}